// round 6
// baseline (speedup 1.0000x reference)
#include <cuda_runtime.h>
#include <math.h>

#define Bn 4
#define CIN 8
#define HH 252
#define WW 2048
#define CM 16
#define DD 12
#define FF 84
#define LL (FF*WW)          /* 172032 */
#define EPSf 1.01e-8f
#define HROW 2056           /* padded row: 4 zero cols each side */
#define HOFF 4

typedef unsigned long long u64;

__device__ __forceinline__ u64 fma2(u64 a, u64 b, u64 c){
    u64 d; asm("fma.rn.f32x2 %0, %1, %2, %3;" : "=l"(d) : "l"(a), "l"(b), "l"(c)); return d;
}
__device__ __forceinline__ u64 pk2(float lo, float hi){
    u64 r; asm("mov.b64 %0, {%1, %2};" : "=l"(r) : "f"(lo), "f"(hi)); return r;
}
__device__ __forceinline__ void upk2(u64 v, float& lo, float& hi){
    asm("mov.b64 {%0, %1}, %2;" : "=f"(lo), "=f"(hi) : "l"(v));
}
__device__ __forceinline__ float wredsum(float v){
    #pragma unroll
    for (int o = 16; o > 0; o >>= 1) v += __shfl_xor_sync(0xffffffffu, v, o);
    return v;
}
__device__ __forceinline__ float wredmax(float v){
    #pragma unroll
    for (int o = 16; o > 0; o >>= 1) v = fmaxf(v, __shfl_xor_sync(0xffffffffu, v, o));
    return v;
}
__device__ __forceinline__ float sigm(float x){
    float t;
    asm("tanh.approx.f32 %0, %1;" : "=f"(t) : "f"(x*0.5f));
    return fmaf(0.5f, t, 0.5f);
}
__device__ __forceinline__ float lrelu(float v){ return v >= 0.f ? v : 0.01f*v; }

// ------------- scratch (device globals; zero-initialized at load) -------------
__device__ __align__(16) float g_h [(size_t)Bn*CM*HH*HROW];  // padded, borders stay 0
__device__ __align__(16) float g_q [(size_t)Bn*LL*DD];
__device__ __align__(16) float g_k [(size_t)Bn*LL*DD];
__device__ __align__(16) float g_v [(size_t)Bn*LL*DD];
__device__ float g_si[(size_t)Bn*LL];
__device__ float g_cs[(size_t)Bn*LL];
__device__ float g_msum[Bn], g_sumexp[Bn];
__device__ float g_qsum[Bn][DD], g_ksum[Bn][DD], g_sq[Bn][DD], g_skv[Bn][DD];
__device__ float g_kvm[Bn][DD*DD];
__device__ float g_M[Bn][DD*DD];
__device__ int   g_maxcs[Bn];

// ------------- K0: zero accumulators -------------
__global__ void k_init(){
    int t = threadIdx.x;
    if (t < Bn){ g_msum[t]=0.f; g_sumexp[t]=0.f; g_maxcs[t]=0; }
    if (t < Bn*DD){
        ((float*)g_qsum)[t]=0.f; ((float*)g_ksum)[t]=0.f;
        ((float*)g_sq)[t]=0.f;   ((float*)g_skv)[t]=0.f;
    }
    if (t < Bn*DD*DD) ((float*)g_kvm)[t]=0.f;
}

// ------------- mask sum per batch -------------
__global__ void __launch_bounds__(256) k_msum(const float* __restrict__ frame){
    int b = blockIdx.y;
    int i = (blockIdx.x*256 + threadIdx.x)*4;
    float4 v = *(const float4*)(frame + (size_t)b*LL + i);
    float s = v.x + v.y + v.z + v.w;
    s = wredsum(s);
    __shared__ float sr;
    if (threadIdx.x == 0) sr = 0.f;
    __syncthreads();
    if ((threadIdx.x & 31) == 0) atomicAdd(&sr, s);
    __syncthreads();
    if (threadIdx.x == 0) atomicAdd(&g_msum[b], sr);
}

// ------------- K1: conv5x5(same) + BN + LeakyReLU, f32x2-packed -------------
__global__ void __launch_bounds__(256,2) k_conv1(
    const float* __restrict__ x, const float* __restrict__ wpre,
    const float* __restrict__ bpre, const float* __restrict__ gam,
    const float* __restrict__ bet,  const float* __restrict__ mean,
    const float* __restrict__ var)
{
    extern __shared__ float sm1[];
    float* xs = sm1;                        // 8*12*132 = 12672 floats
    u64*   ws = (u64*)(sm1 + 12672);        // 3200 u64, 16B-aligned
    int b = blockIdx.z, r0 = blockIdx.y*8, c0 = blockIdx.x*128;
    int tid = threadIdx.x;

    for (int i = tid; i < 3200; i += 256){
        int o = i & 15, rest = i >> 4;
        int kw = rest % 5, kh = (rest/5) % 5, c = rest/25;
        float w = wpre[((o*CIN + c)*5 + kh)*5 + kw];
        ws[i] = pk2(w, w);
    }
    for (int i = tid; i < 12672; i += 256){
        int cc = i % 132; int t2 = i / 132; int rr = t2 % 12; int c = t2 / 12;
        int gr = r0 - 2 + rr, gc = c0 - 2 + cc;
        float v = 0.f;
        if (gr >= 0 && gr < HH && gc >= 0 && gc < WW)
            v = x[(((size_t)b*CIN + c)*HH + gr)*WW + gc];
        xs[i] = v;
    }
    __syncthreads();

    int r = tid >> 5, cg = tid & 31, col0 = cg*4;
    u64 acc[16][2];
    #pragma unroll
    for (int o = 0; o < 16; o++){ acc[o][0]=0ull; acc[o][1]=0ull; }

    #pragma unroll 1
    for (int c = 0; c < 8; c++){
        #pragma unroll
        for (int kh = 0; kh < 5; kh++){
            const float* row = xs + (c*12 + r + kh)*132 + col0;
            float4 A = *(const float4*)row;
            float4 Bv = *(const float4*)(row + 4);
            float a0=A.x,a1=A.y,a2=A.z,a3=A.w,a4=Bv.x,a5=Bv.y,a6=Bv.z,a7=Bv.w;
            u64 P0[5] = {pk2(a0,a1),pk2(a1,a2),pk2(a2,a3),pk2(a3,a4),pk2(a4,a5)};
            u64 P1[5] = {pk2(a2,a3),pk2(a3,a4),pk2(a4,a5),pk2(a5,a6),pk2(a6,a7)};
            const u64* wbase = ws + (c*5 + kh)*80;
            #pragma unroll
            for (int kw = 0; kw < 5; kw++){
                const ulonglong2* wrow = (const ulonglong2*)(wbase + kw*16);
                #pragma unroll
                for (int o2 = 0; o2 < 8; o2++){
                    ulonglong2 wv = wrow[o2];
                    acc[2*o2  ][0] = fma2(P0[kw], wv.x, acc[2*o2  ][0]);
                    acc[2*o2  ][1] = fma2(P1[kw], wv.x, acc[2*o2  ][1]);
                    acc[2*o2+1][0] = fma2(P0[kw], wv.y, acc[2*o2+1][0]);
                    acc[2*o2+1][1] = fma2(P1[kw], wv.y, acc[2*o2+1][1]);
                }
            }
        }
    }
    int orow = r0 + r;
    if (orow < HH){
        #pragma unroll
        for (int o = 0; o < 16; o++){
            float s  = gam[o] * rsqrtf(var[o] + 1e-5f);
            float c2 = bet[o] + (bpre[o] - mean[o]) * s;
            float v0,v1,v2,v3;
            upk2(acc[o][0], v0, v1); upk2(acc[o][1], v2, v3);
            float4 o4;
            o4.x = lrelu(v0*s + c2); o4.y = lrelu(v1*s + c2);
            o4.z = lrelu(v2*s + c2); o4.w = lrelu(v3*s + c2);
            *(float4*)(g_h + (((size_t)b*CM + o)*HH + orow)*HROW + HOFF + c0 + col0) = o4;
        }
    }
}

// ------------- store helper: 4 positions x 12 channels, packed pairs -------------
__device__ __forceinline__ void store4pos(float* dst, const u64 st[12][2]){
    #pragma unroll
    for (int pk = 0; pk < 2; pk++){
        #pragma unroll
        for (int z = 0; z < 3; z++){
            float a0,b0,a1,b1,a2,b2,a3,b3;
            upk2(st[4*z  ][pk],a0,b0); upk2(st[4*z+1][pk],a1,b1);
            upk2(st[4*z+2][pk],a2,b2); upk2(st[4*z+3][pk],a3,b3);
            *(float4*)(dst + (2*pk  )*12 + 4*z) = make_float4(a0,a1,a2,a3);
            *(float4*)(dst + (2*pk+1)*12 + 4*z) = make_float4(b0,b1,b2,b3);
        }
    }
}

// ------------- K2: FUSED Q/KV convs + masknorm + projections + sums -------------
// grid (2, 84, 4), block 256, 1024 cols/block.
// Phase 1: conv, 8 pos/thread (warps 0-3 q, 4-7 kv) -> smem exchange.
// Phase 2: 4 pos/thread, packed projections with transposed LDS.128 weights.
#define QKV_SMEM (3456*8 + 432*8 + 24576*4 + 96*4)
__global__ void __launch_bounds__(256,1) k_qkv2(
    const float* __restrict__ wq,  const float* __restrict__ bqc,
    const float* __restrict__ wkv, const float* __restrict__ bkvc,
    const float* __restrict__ frame, const float* __restrict__ Tp,
    const float* __restrict__ fwq, const float* __restrict__ fbq,
    const float* __restrict__ fwk, const float* __restrict__ fbk,
    const float* __restrict__ fwv, const float* __restrict__ fbv)
{
    extern __shared__ __align__(16) char smraw[];
    u64*   ws  = (u64*)smraw;                  // 3456
    u64*   fwT = ws + 3456;                    // 432, [proj][j][d] packed (w,w)
    float* ex  = (float*)(fwT + 432);          // 24*1024 floats
    float* cbs = ex + 24576;                   // 24
    float* fbs = cbs + 24;                     // 36
    float* red = fbs + 36;                     // 24

    int b = blockIdx.z, f = blockIdx.y;
    int tid = threadIdx.x;

    for (int i = tid; i < 3456; i += 256){
        int half2 = i / 1728, rem = i % 1728;
        int d = rem % 12, r2 = rem / 12;
        int kw = r2 % 3, kh = (r2/3) % 3, c = r2/9;
        const float* srcw = half2 ? wkv : wq;
        float w = srcw[((d*CM + c)*3 + kh)*3 + kw];
        ws[i] = pk2(w, w);
    }
    for (int i = tid; i < 432; i += 256){
        int wsel = i / 144, rem = i % 144, j = rem / 12, d = rem % 12;
        float w = (wsel == 0 ? fwq : (wsel == 1 ? fwk : fwv))[d*12 + j];
        fwT[i] = pk2(w, w);
    }
    if (tid < 24) cbs[tid] = (tid < 12) ? bqc[tid] : bkvc[tid-12];
    if (tid < 36) fbs[tid] = (tid < 12) ? fbq[tid] : (tid < 24 ? fbk[tid-12] : fbv[tid-24]);
    if (tid < 24) red[tid] = 0.f;
    __syncthreads();

    // ---- Phase 1: conv, 8 positions/thread ----
    {
        int half = tid >> 7, pt = tid & 127, lane = tid & 31;
        int t0 = blockIdx.x*1024 + pt*8;
        u64 acc[12][4];
        #pragma unroll
        for (int d = 0; d < 12; d++){
            u64 bb = pk2(cbs[half*12+d], cbs[half*12+d]);
            acc[d][0]=bb; acc[d][1]=bb; acc[d][2]=bb; acc[d][3]=bb;
        }
        const float* hb = g_h + (((size_t)b*CM)*HH + 3*f)*HROW + HOFF + t0;
        const u64* wsh = ws + half*1728;
        #pragma unroll 1
        for (int c = 0; c < 16; c++){
            #pragma unroll
            for (int kh = 0; kh < 3; kh++){
                const float* row = hb + ((size_t)c*HH + kh)*HROW;
                float4 F1 = *(const float4*)row;
                float4 F2 = *(const float4*)(row + 4);
                float xm1 = __shfl_up_sync(0xffffffffu, F2.w, 1);
                if (lane == 0)  xm1 = row[-1];
                float xp8 = __shfl_down_sync(0xffffffffu, F1.x, 1);
                if (lane == 31) xp8 = row[8];
                u64 P0[4] = {pk2(xm1,F1.x), pk2(F1.y,F1.z), pk2(F1.w,F2.x), pk2(F2.y,F2.z)};
                u64 P1[4] = {pk2(F1.x,F1.y), pk2(F1.z,F1.w), pk2(F2.x,F2.y), pk2(F2.z,F2.w)};
                u64 P2[4] = {P0[1], P0[2], P0[3], pk2(F2.w,xp8)};
                const u64* wp = wsh + (c*3 + kh)*36;
                #pragma unroll
                for (int kw = 0; kw < 3; kw++){
                    const u64* Pk = (kw==0) ? P0 : ((kw==1) ? P1 : P2);
                    const ulonglong2* w2 = (const ulonglong2*)(wp + kw*12);
                    #pragma unroll
                    for (int dp = 0; dp < 6; dp++){
                        ulonglong2 wv = w2[dp];
                        #pragma unroll
                        for (int i = 0; i < 4; i++){
                            acc[2*dp  ][i] = fma2(Pk[i], wv.x, acc[2*dp  ][i]);
                            acc[2*dp+1][i] = fma2(Pk[i], wv.y, acc[2*dp+1][i]);
                        }
                    }
                }
            }
        }
        float* exb = ex + (half*12)*1024 + pt*8;
        #pragma unroll
        for (int d = 0; d < 12; d++){
            float v0,v1,v2,v3,v4,v5,v6,v7;
            upk2(acc[d][0],v0,v1); upk2(acc[d][1],v2,v3);
            upk2(acc[d][2],v4,v5); upk2(acc[d][3],v6,v7);
            *(float4*)(exb + d*1024)     = make_float4(v0,v1,v2,v3);
            *(float4*)(exb + d*1024 + 4) = make_float4(v4,v5,v6,v7);
        }
    }
    __syncthreads();

    // ---- Phase 2: masknorm + projections (4 positions/thread) ----
    {
        int lp = tid*4;
        size_t l0 = (size_t)f*WW + blockIdx.x*1024 + lp;
        size_t gbase = ((size_t)b*LL + l0)*12;
        u64 cin[12][2];

        // Q projection + sigmoid
        #pragma unroll
        for (int d = 0; d < 12; d++){
            ulonglong2 t = *(const ulonglong2*)(ex + d*1024 + lp);
            cin[d][0]=t.x; cin[d][1]=t.y;
        }
        {
            u64 st[12][2]; float ssum[12];
            #pragma unroll
            for (int j = 0; j < 12; j++){
                u64 a0 = pk2(fbs[j], fbs[j]), a1 = a0;
                const ulonglong2* wv = (const ulonglong2*)(fwT + j*12);
                #pragma unroll
                for (int dp = 0; dp < 6; dp++){
                    ulonglong2 w = wv[dp];
                    a0 = fma2(cin[2*dp  ][0], w.x, a0); a1 = fma2(cin[2*dp  ][1], w.x, a1);
                    a0 = fma2(cin[2*dp+1][0], w.y, a0); a1 = fma2(cin[2*dp+1][1], w.y, a1);
                }
                float x0,x1,x2,x3; upk2(a0,x0,x1); upk2(a1,x2,x3);
                x0=sigm(x0); x1=sigm(x1); x2=sigm(x2); x3=sigm(x3);
                st[j][0]=pk2(x0,x1); st[j][1]=pk2(x2,x3);
                ssum[j] = (x0+x1) + (x2+x3);
            }
            store4pos(g_q + gbase, st);
            #pragma unroll
            for (int j = 0; j < 12; j++){
                float s = wredsum(ssum[j]);
                if ((tid & 31) == 0) atomicAdd(&red[j], s);
            }
        }

        // load kv conv outputs, masknorm scale
        u64 s2a = pk2(EPSf,EPSf), s2b = s2a;
        #pragma unroll
        for (int d = 0; d < 12; d++){
            ulonglong2 t = *(const ulonglong2*)(ex + (12+d)*1024 + lp);
            cin[d][0]=t.x; cin[d][1]=t.y;
            s2a = fma2(t.x, t.x, s2a); s2b = fma2(t.y, t.y, s2b);
        }
        float s0,s1,s2,s3; upk2(s2a,s0,s1); upk2(s2b,s2,s3);
        float cf = Tp[0] / g_msum[b];
        float4 mk = *(const float4*)(frame + (size_t)b*LL + l0);
        u64 sc0 = pk2(mk.x*cf*rsqrtf(s0), mk.y*cf*rsqrtf(s1));
        u64 sc1 = pk2(mk.z*cf*rsqrtf(s2), mk.w*cf*rsqrtf(s3));
        #pragma unroll
        for (int d = 0; d < 12; d++){
            cin[d][0] = fma2(cin[d][0], sc0, 0ull);
            cin[d][1] = fma2(cin[d][1], sc1, 0ull);
        }

        // K projection + sigmoid
        {
            u64 st[12][2]; float ssum[12];
            #pragma unroll
            for (int j = 0; j < 12; j++){
                u64 a0 = pk2(fbs[12+j], fbs[12+j]), a1 = a0;
                const ulonglong2* wv = (const ulonglong2*)(fwT + 144 + j*12);
                #pragma unroll
                for (int dp = 0; dp < 6; dp++){
                    ulonglong2 w = wv[dp];
                    a0 = fma2(cin[2*dp  ][0], w.x, a0); a1 = fma2(cin[2*dp  ][1], w.x, a1);
                    a0 = fma2(cin[2*dp+1][0], w.y, a0); a1 = fma2(cin[2*dp+1][1], w.y, a1);
                }
                float x0,x1,x2,x3; upk2(a0,x0,x1); upk2(a1,x2,x3);
                x0=sigm(x0); x1=sigm(x1); x2=sigm(x2); x3=sigm(x3);
                st[j][0]=pk2(x0,x1); st[j][1]=pk2(x2,x3);
                ssum[j] = (x0+x1) + (x2+x3);
            }
            store4pos(g_k + gbase, st);
            #pragma unroll
            for (int j = 0; j < 12; j++){
                float s = wredsum(ssum[j]);
                if ((tid & 31) == 0) atomicAdd(&red[12+j], s);
            }
        }

        // V projection
        {
            u64 st[12][2];
            #pragma unroll
            for (int j = 0; j < 12; j++){
                u64 a0 = pk2(fbs[24+j], fbs[24+j]), a1 = a0;
                const ulonglong2* wv = (const ulonglong2*)(fwT + 288 + j*12);
                #pragma unroll
                for (int dp = 0; dp < 6; dp++){
                    ulonglong2 w = wv[dp];
                    a0 = fma2(cin[2*dp  ][0], w.x, a0); a1 = fma2(cin[2*dp  ][1], w.x, a1);
                    a0 = fma2(cin[2*dp+1][0], w.y, a0); a1 = fma2(cin[2*dp+1][1], w.y, a1);
                }
                st[j][0]=a0; st[j][1]=a1;
            }
            store4pos(g_v + gbase, st);
        }
    }
    __syncthreads();
    if (tid < 12)       atomicAdd(&g_qsum[b][tid], red[tid]);
    else if (tid < 24)  atomicAdd(&g_ksum[b][tid-12], red[tid]);
}

// ------------- K3: sink_in / src_out + sq/skv sums -------------
__global__ void __launch_bounds__(256) k3(){
    int b = blockIdx.y;
    int l = blockIdx.x*256 + threadIdx.x;
    int tid = threadIdx.x;
    __shared__ float kE[12], qE[12], red[24];
    if (tid < 12){ kE[tid] = g_ksum[b][tid] + EPSf; qE[tid] = g_qsum[b][tid] + EPSf; }
    if (tid < 24) red[tid] = 0.f;
    __syncthreads();
    size_t base = ((size_t)b*LL + l)*12;
    float q[12], k[12];
    #pragma unroll
    for (int z = 0; z < 3; z++){
        float4 a = *(const float4*)(g_q + base + 4*z);
        float4 c = *(const float4*)(g_k + base + 4*z);
        q[4*z]=a.x; q[4*z+1]=a.y; q[4*z+2]=a.z; q[4*z+3]=a.w;
        k[4*z]=c.x; k[4*z+1]=c.y; k[4*z+2]=c.z; k[4*z+3]=c.w;
    }
    float si = 0.f, so = 0.f;
    #pragma unroll
    for (int d = 0; d < 12; d++){ si += (q[d]+EPSf)*kE[d]; so += (k[d]+EPSf)*qE[d]; }
    si = 1.f/si; so = 1.f/so;
    g_si[(size_t)b*LL + l] = si;
    #pragma unroll
    for (int d = 0; d < 12; d++){
        float sqv = wredsum(q[d]*si), skvv = wredsum(k[d]*so);
        if ((tid & 31) == 0){ atomicAdd(&red[d], sqv); atomicAdd(&red[12+d], skvv); }
    }
    __syncthreads();
    if (tid < 12)      atomicAdd(&g_sq[b][tid], red[tid]);
    else if (tid < 24) atomicAdd(&g_skv[b][tid-12], red[tid]);
}

// ------------- K4: cons_src + global max -------------
__global__ void __launch_bounds__(256) k4(){
    int b = blockIdx.y;
    int l = blockIdx.x*256 + threadIdx.x;
    int tid = threadIdx.x;
    __shared__ float sqE[12];
    __shared__ int redm;
    if (tid < 12) sqE[tid] = g_sq[b][tid] + EPSf;
    if (tid == 0) redm = 0;
    __syncthreads();
    size_t base = ((size_t)b*LL + l)*12;
    float cons = 0.f;
    #pragma unroll
    for (int z = 0; z < 3; z++){
        float4 c = *(const float4*)(g_k + base + 4*z);
        cons += (c.x+EPSf)*sqE[4*z] + (c.y+EPSf)*sqE[4*z+1]
              + (c.z+EPSf)*sqE[4*z+2] + (c.w+EPSf)*sqE[4*z+3];
    }
    g_cs[(size_t)b*LL + l] = cons;
    float m = wredmax(cons);
    if ((tid & 31) == 0) atomicMax(&redm, __float_as_int(m));
    __syncthreads();
    if (tid == 0) atomicMax(&g_maxcs[b], redm);
}

// ------------- K56: sumexp + raw kv outer product (fused) -------------
__global__ void __launch_bounds__(256,1) k56(){
    int b = blockIdx.y;
    int tid = threadIdx.x;
    float mx = __int_as_float(g_maxcs[b]);
    float acc[12][12];
    #pragma unroll
    for (int d = 0; d < 12; d++)
        #pragma unroll
        for (int m = 0; m < 12; m++) acc[d][m] = 0.f;
    float se = 0.f;

    for (int l = blockIdx.x*256 + tid; l < LL; l += 64*256){
        float e = __expf(g_cs[(size_t)b*LL + l] - mx);
        se += e;
        size_t base = ((size_t)b*LL + l)*12;
        float k[12], vm[12];
        #pragma unroll
        for (int z = 0; z < 3; z++){
            float4 a = *(const float4*)(g_k + base + 4*z);
            float4 c = *(const float4*)(g_v + base + 4*z);
            k[4*z]=a.x; k[4*z+1]=a.y; k[4*z+2]=a.z; k[4*z+3]=a.w;
            vm[4*z]=c.x*e; vm[4*z+1]=c.y*e; vm[4*z+2]=c.z*e; vm[4*z+3]=c.w*e;
        }
        #pragma unroll
        for (int d = 0; d < 12; d++)
            #pragma unroll
            for (int m = 0; m < 12; m++) acc[d][m] += k[d]*vm[m];
    }
    __shared__ float red[144];
    __shared__ float sred;
    for (int i = tid; i < 144; i += 256) red[i] = 0.f;
    if (tid == 0) sred = 0.f;
    __syncthreads();
    se = wredsum(se);
    if ((tid & 31) == 0) atomicAdd(&sred, se);
    #pragma unroll
    for (int d = 0; d < 12; d++)
        #pragma unroll
        for (int m = 0; m < 12; m++){
            float v = wredsum(acc[d][m]);
            if ((tid & 31) == 0) atomicAdd(&red[d*12+m], v);
        }
    __syncthreads();
    if (tid < 144) atomicAdd(&g_kvm[b][tid], red[tid]);
    if (tid == 0)  atomicAdd(&g_sumexp[b], sred);
}

// ------------- Kmm: M = kv_norm @ Wo -------------
__global__ void kmm(const float* __restrict__ fwo){
    int b = blockIdx.x, tid = threadIdx.x;
    float norm = 172032.0f / g_sumexp[b];
    int d = tid/12, j = tid%12;
    float s = 0.f;
    #pragma unroll
    for (int m = 0; m < 12; m++) s += g_kvm[b][d*12+m]*fwo[m*12+j];
    g_M[b][tid] = s * norm;
}

// ------------- K7: epilogue, write output -------------
__global__ void __launch_bounds__(256) k7(const float* __restrict__ fbo, float* __restrict__ out){
    int b = blockIdx.y;
    int l = blockIdx.x*256 + threadIdx.x;
    int tid = threadIdx.x;
    __shared__ float Ms[144], skvE[12], bos[12];
    if (tid < 144) Ms[tid] = g_M[b][tid];
    if (tid < 12){ skvE[tid] = g_skv[b][tid] + EPSf; bos[tid] = fbo[tid]; }
    __syncthreads();
    size_t base = ((size_t)b*LL + l)*12;
    float q[12];
    #pragma unroll
    for (int z = 0; z < 3; z++){
        float4 a = *(const float4*)(g_q + base + 4*z);
        q[4*z]=a.x; q[4*z+1]=a.y; q[4*z+2]=a.z; q[4*z+3]=a.w;
    }
    float cs = 0.f;
    #pragma unroll
    for (int d = 0; d < 12; d++) cs += (q[d]+EPSf)*skvE[d];
    float scale = g_si[(size_t)b*LL + l] * sigm(cs);
    #pragma unroll
    for (int j = 0; j < 12; j++){
        float o = 0.f;
        #pragma unroll
        for (int d = 0; d < 12; d++) o += q[d]*Ms[d*12+j];
        out[((size_t)b*DD + j)*LL + l] = bos[j] + scale*o;
    }
}

extern "C" void kernel_launch(void* const* d_in, const int* in_sizes, int n_in,
                              void* d_out, int out_size){
    const float* x     = (const float*)d_in[0];
    const float* frame = (const float*)d_in[1];
    const float* wpre  = (const float*)d_in[2];
    const float* bpre  = (const float*)d_in[3];
    const float* gam   = (const float*)d_in[4];
    const float* bet   = (const float*)d_in[5];
    const float* mean  = (const float*)d_in[6];
    const float* var   = (const float*)d_in[7];
    const float* Tp    = (const float*)d_in[8];
    const float* wq    = (const float*)d_in[9];
    const float* bqc   = (const float*)d_in[10];
    const float* wkv   = (const float*)d_in[11];
    const float* bkvc  = (const float*)d_in[12];
    const float* fwq   = (const float*)d_in[13];
    const float* fbq   = (const float*)d_in[14];
    const float* fwk   = (const float*)d_in[15];
    const float* fbk   = (const float*)d_in[16];
    const float* fwv   = (const float*)d_in[17];
    const float* fbv   = (const float*)d_in[18];
    const float* fwo   = (const float*)d_in[19];
    const float* fbo   = (const float*)d_in[20];
    float* out = (float*)d_out;

    cudaFuncSetAttribute(k_conv1, cudaFuncAttributeMaxDynamicSharedMemorySize, 76288);
    cudaFuncSetAttribute(k_qkv2,  cudaFuncAttributeMaxDynamicSharedMemorySize, QKV_SMEM);

    k_init  <<<1, 1024>>>();
    k_msum  <<<dim3(168, Bn), 256>>>(frame);
    k_conv1 <<<dim3(16, 32, Bn), 256, 76288>>>(x, wpre, bpre, gam, bet, mean, var);
    k_qkv2  <<<dim3(2, FF, Bn), 256, QKV_SMEM>>>(wq, bqc, wkv, bkvc, frame, Tp,
                                                 fwq, fbq, fwk, fbk, fwv, fbv);
    k3  <<<dim3(672, Bn), 256>>>();
    k4  <<<dim3(672, Bn), 256>>>();
    k56 <<<dim3(64, Bn), 256>>>();
    kmm <<<Bn, 144>>>(fwo);
    k7  <<<dim3(672, Bn), 256>>>(fbo, out);
    (void)in_sizes; (void)n_in; (void)out_size;
}

// round 7
// speedup vs baseline: 1.1039x; 1.1039x over previous
#include <cuda_runtime.h>
#include <math.h>

#define Bn 4
#define CIN 8
#define HH 252
#define WW 2048
#define CM 16
#define DD 12
#define FF 84
#define LL (FF*WW)          /* 172032 */
#define EPSf 1.01e-8f
#define HROW 2056           /* padded row: 4 zero cols each side */
#define HOFF 4

typedef unsigned long long u64;

__device__ __forceinline__ u64 fma2(u64 a, u64 b, u64 c){
    u64 d; asm("fma.rn.f32x2 %0, %1, %2, %3;" : "=l"(d) : "l"(a), "l"(b), "l"(c)); return d;
}
__device__ __forceinline__ u64 pk2(float lo, float hi){
    u64 r; asm("mov.b64 %0, {%1, %2};" : "=l"(r) : "f"(lo), "f"(hi)); return r;
}
__device__ __forceinline__ void upk2(u64 v, float& lo, float& hi){
    asm("mov.b64 {%0, %1}, %2;" : "=f"(lo), "=f"(hi) : "l"(v));
}
__device__ __forceinline__ float wredsum(float v){
    #pragma unroll
    for (int o = 16; o > 0; o >>= 1) v += __shfl_xor_sync(0xffffffffu, v, o);
    return v;
}
__device__ __forceinline__ float wredmax(float v){
    #pragma unroll
    for (int o = 16; o > 0; o >>= 1) v = fmaxf(v, __shfl_xor_sync(0xffffffffu, v, o));
    return v;
}
__device__ __forceinline__ float sigm(float x){
    float t;
    asm("tanh.approx.f32 %0, %1;" : "=f"(t) : "f"(x*0.5f));
    return fmaf(0.5f, t, 0.5f);
}
__device__ __forceinline__ float lrelu(float v){ return v >= 0.f ? v : 0.01f*v; }

// ------------- scratch (device globals; zero-initialized at load) -------------
__device__ __align__(16) float g_h [(size_t)Bn*CM*HH*HROW];  // padded, borders stay 0
__device__ __align__(16) float g_q [(size_t)Bn*LL*DD];
__device__ __align__(16) float g_k [(size_t)Bn*LL*DD];
__device__ __align__(16) float g_v [(size_t)Bn*LL*DD];
__device__ float g_si[(size_t)Bn*LL];
__device__ float g_cs[(size_t)Bn*LL];
__device__ float g_msum[Bn], g_sumexp[Bn];
__device__ float g_qsum[Bn][DD], g_ksum[Bn][DD], g_sq[Bn][DD], g_skv[Bn][DD];
__device__ float g_kvm[Bn][DD*DD];
__device__ float g_M[Bn][DD*DD];
__device__ int   g_maxcs[Bn];

// ------------- K0: zero accumulators -------------
__global__ void k_init(){
    int t = threadIdx.x;
    if (t < Bn){ g_msum[t]=0.f; g_sumexp[t]=0.f; g_maxcs[t]=0; }
    if (t < Bn*DD){
        ((float*)g_qsum)[t]=0.f; ((float*)g_ksum)[t]=0.f;
        ((float*)g_sq)[t]=0.f;   ((float*)g_skv)[t]=0.f;
    }
    if (t < Bn*DD*DD) ((float*)g_kvm)[t]=0.f;
}

// ------------- mask sum per batch -------------
__global__ void __launch_bounds__(256) k_msum(const float* __restrict__ frame){
    int b = blockIdx.y;
    int i = (blockIdx.x*256 + threadIdx.x)*4;
    float4 v = *(const float4*)(frame + (size_t)b*LL + i);
    float s = v.x + v.y + v.z + v.w;
    s = wredsum(s);
    __shared__ float sr;
    if (threadIdx.x == 0) sr = 0.f;
    __syncthreads();
    if ((threadIdx.x & 31) == 0) atomicAdd(&sr, s);
    __syncthreads();
    if (threadIdx.x == 0) atomicAdd(&g_msum[b], sr);
}

// ------------- K1: conv5x5(same) + BN + LeakyReLU, f32x2-packed -------------
__global__ void __launch_bounds__(256,2) k_conv1(
    const float* __restrict__ x, const float* __restrict__ wpre,
    const float* __restrict__ bpre, const float* __restrict__ gam,
    const float* __restrict__ bet,  const float* __restrict__ mean,
    const float* __restrict__ var)
{
    extern __shared__ float sm1[];
    float* xs = sm1;                        // 8*12*132 = 12672 floats
    u64*   ws = (u64*)(sm1 + 12672);        // 3200 u64, 16B-aligned
    int b = blockIdx.z, r0 = blockIdx.y*8, c0 = blockIdx.x*128;
    int tid = threadIdx.x;

    for (int i = tid; i < 3200; i += 256){
        int o = i & 15, rest = i >> 4;
        int kw = rest % 5, kh = (rest/5) % 5, c = rest/25;
        float w = wpre[((o*CIN + c)*5 + kh)*5 + kw];
        ws[i] = pk2(w, w);
    }
    for (int i = tid; i < 12672; i += 256){
        int cc = i % 132; int t2 = i / 132; int rr = t2 % 12; int c = t2 / 12;
        int gr = r0 - 2 + rr, gc = c0 - 2 + cc;
        float v = 0.f;
        if (gr >= 0 && gr < HH && gc >= 0 && gc < WW)
            v = x[(((size_t)b*CIN + c)*HH + gr)*WW + gc];
        xs[i] = v;
    }
    __syncthreads();

    int r = tid >> 5, cg = tid & 31, col0 = cg*4;
    u64 acc[16][2];
    #pragma unroll
    for (int o = 0; o < 16; o++){ acc[o][0]=0ull; acc[o][1]=0ull; }

    #pragma unroll 1
    for (int c = 0; c < 8; c++){
        #pragma unroll
        for (int kh = 0; kh < 5; kh++){
            const float* row = xs + (c*12 + r + kh)*132 + col0;
            float4 A = *(const float4*)row;
            float4 Bv = *(const float4*)(row + 4);
            float a0=A.x,a1=A.y,a2=A.z,a3=A.w,a4=Bv.x,a5=Bv.y,a6=Bv.z,a7=Bv.w;
            u64 P0[5] = {pk2(a0,a1),pk2(a1,a2),pk2(a2,a3),pk2(a3,a4),pk2(a4,a5)};
            u64 P1[5] = {pk2(a2,a3),pk2(a3,a4),pk2(a4,a5),pk2(a5,a6),pk2(a6,a7)};
            const u64* wbase = ws + (c*5 + kh)*80;
            #pragma unroll
            for (int kw = 0; kw < 5; kw++){
                const ulonglong2* wrow = (const ulonglong2*)(wbase + kw*16);
                #pragma unroll
                for (int o2 = 0; o2 < 8; o2++){
                    ulonglong2 wv = wrow[o2];
                    acc[2*o2  ][0] = fma2(P0[kw], wv.x, acc[2*o2  ][0]);
                    acc[2*o2  ][1] = fma2(P1[kw], wv.x, acc[2*o2  ][1]);
                    acc[2*o2+1][0] = fma2(P0[kw], wv.y, acc[2*o2+1][0]);
                    acc[2*o2+1][1] = fma2(P1[kw], wv.y, acc[2*o2+1][1]);
                }
            }
        }
    }
    int orow = r0 + r;
    if (orow < HH){
        #pragma unroll
        for (int o = 0; o < 16; o++){
            float s  = gam[o] * rsqrtf(var[o] + 1e-5f);
            float c2 = bet[o] + (bpre[o] - mean[o]) * s;
            float v0,v1,v2,v3;
            upk2(acc[o][0], v0, v1); upk2(acc[o][1], v2, v3);
            float4 o4;
            o4.x = lrelu(v0*s + c2); o4.y = lrelu(v1*s + c2);
            o4.z = lrelu(v2*s + c2); o4.w = lrelu(v3*s + c2);
            *(float4*)(g_h + (((size_t)b*CM + o)*HH + orow)*HROW + HOFF + c0 + col0) = o4;
        }
    }
}

// ------------- K2: FUSED Q/KV convs + masknorm + projections + sums -------------
// grid (4, 84, 4), block 256. Phase 1: conv 4 pos/thread (warps 0-3 q, 4-7 kv).
// Phase 2: 2 pos/thread, packed projections, transposed LDS.128 weights.
#define QKV_SMEM (3456*8 + 432*8 + 12288*4 + 96*4)
__global__ void __launch_bounds__(256,2) k_qkv2(
    const float* __restrict__ wq,  const float* __restrict__ bqc,
    const float* __restrict__ wkv, const float* __restrict__ bkvc,
    const float* __restrict__ frame, const float* __restrict__ Tp,
    const float* __restrict__ fwq, const float* __restrict__ fbq,
    const float* __restrict__ fwk, const float* __restrict__ fbk,
    const float* __restrict__ fwv, const float* __restrict__ fbv)
{
    extern __shared__ __align__(16) char smraw[];
    u64*   ws  = (u64*)smraw;                  // 3456
    u64*   fwT = ws + 3456;                    // 432, [proj][j][d] packed (w,w)
    float* ex  = (float*)(fwT + 432);          // 24*512 floats
    float* cbs = ex + 12288;                   // 24
    float* fbs = cbs + 24;                     // 36
    float* red = fbs + 36;                     // 24

    int b = blockIdx.z, f = blockIdx.y;
    int tid = threadIdx.x;

    for (int i = tid; i < 3456; i += 256){
        int half2 = i / 1728, rem = i % 1728;
        int d = rem % 12, r2 = rem / 12;
        int kw = r2 % 3, kh = (r2/3) % 3, c = r2/9;
        const float* srcw = half2 ? wkv : wq;
        float w = srcw[((d*CM + c)*3 + kh)*3 + kw];
        ws[i] = pk2(w, w);
    }
    for (int i = tid; i < 432; i += 256){
        int wsel = i / 144, rem = i % 144, j = rem / 12, d = rem % 12;
        float w = (wsel == 0 ? fwq : (wsel == 1 ? fwk : fwv))[d*12 + j];
        fwT[i] = pk2(w, w);
    }
    if (tid < 24) cbs[tid] = (tid < 12) ? bqc[tid] : bkvc[tid-12];
    if (tid < 36) fbs[tid] = (tid < 12) ? fbq[tid] : (tid < 24 ? fbk[tid-12] : fbv[tid-24]);
    if (tid < 24) red[tid] = 0.f;
    __syncthreads();

    // ---- Phase 1: conv, 4 positions/thread ----
    {
        int half = tid >> 7, pt = tid & 127, lane = tid & 31;
        int t0 = blockIdx.x*512 + pt*4;
        u64 acc[12][2];
        #pragma unroll
        for (int d = 0; d < 12; d++){
            u64 bb = pk2(cbs[half*12+d], cbs[half*12+d]);
            acc[d][0] = bb; acc[d][1] = bb;
        }
        const float* hb = g_h + (((size_t)b*CM)*HH + 3*f)*HROW + HOFF + t0;
        const u64* wsh = ws + half*1728;
        #pragma unroll 1
        for (int c = 0; c < 16; c++){
            #pragma unroll
            for (int kh = 0; kh < 3; kh++){
                const float* row = hb + ((size_t)c*HH + kh)*HROW;
                float4 F = *(const float4*)row;
                float xm1 = __shfl_up_sync(0xffffffffu, F.w, 1);
                if (lane == 0)  xm1 = row[-1];
                float xp4 = __shfl_down_sync(0xffffffffu, F.x, 1);
                if (lane == 31) xp4 = row[4];
                u64 P[3][2];
                P[0][0] = pk2(xm1, F.x); P[0][1] = pk2(F.y, F.z);
                P[1][0] = pk2(F.x, F.y); P[1][1] = pk2(F.z, F.w);
                P[2][0] = pk2(F.y, F.z); P[2][1] = pk2(F.w, xp4);
                const u64* wp = wsh + (c*3 + kh)*36;
                #pragma unroll
                for (int kw = 0; kw < 3; kw++){
                    const ulonglong2* w2 = (const ulonglong2*)(wp + kw*12);
                    #pragma unroll
                    for (int dp = 0; dp < 6; dp++){
                        ulonglong2 wv = w2[dp];
                        acc[2*dp  ][0] = fma2(P[kw][0], wv.x, acc[2*dp  ][0]);
                        acc[2*dp  ][1] = fma2(P[kw][1], wv.x, acc[2*dp  ][1]);
                        acc[2*dp+1][0] = fma2(P[kw][0], wv.y, acc[2*dp+1][0]);
                        acc[2*dp+1][1] = fma2(P[kw][1], wv.y, acc[2*dp+1][1]);
                    }
                }
            }
        }
        float* exb = ex + (half*12)*512 + pt*4;
        #pragma unroll
        for (int d = 0; d < 12; d++){
            float v0,v1,v2,v3;
            upk2(acc[d][0], v0, v1); upk2(acc[d][1], v2, v3);
            *(float4*)(exb + d*512) = make_float4(v0,v1,v2,v3);
        }
    }
    __syncthreads();

    // ---- Phase 2: masknorm + projections (2 positions/thread, packed) ----
    {
        int lp = tid*2;
        size_t l0 = (size_t)f*WW + blockIdx.x*512 + lp;
        u64 inq[12], ckv[12];
        #pragma unroll
        for (int d = 0; d < 12; d++) inq[d] = *(const u64*)(ex + d*512 + lp);
        u64 s2p = pk2(EPSf, EPSf);
        #pragma unroll
        for (int d = 0; d < 12; d++){
            ckv[d] = *(const u64*)(ex + (12+d)*512 + lp);
            s2p = fma2(ckv[d], ckv[d], s2p);
        }
        float s20, s21; upk2(s2p, s20, s21);
        float cf = Tp[0] / g_msum[b];
        float2 mk = *(const float2*)(frame + (size_t)b*LL + l0);
        u64 sc2 = pk2(mk.x*cf*rsqrtf(s20), mk.y*cf*rsqrtf(s21));

        size_t gbase = ((size_t)b*LL + l0)*12;

        // Q projection + sigmoid
        {
            u64 st[12]; float qs[12];
            #pragma unroll
            for (int j = 0; j < 12; j++){
                u64 a = pk2(fbs[j], fbs[j]);
                const ulonglong2* wv = (const ulonglong2*)(fwT + j*12);
                #pragma unroll
                for (int dp = 0; dp < 6; dp++){
                    ulonglong2 w = wv[dp];
                    a = fma2(inq[2*dp  ], w.x, a);
                    a = fma2(inq[2*dp+1], w.y, a);
                }
                float x0, x1; upk2(a, x0, x1);
                x0 = sigm(x0); x1 = sigm(x1);
                st[j] = pk2(x0, x1); qs[j] = x0 + x1;
            }
            #pragma unroll
            for (int z = 0; z < 3; z++){
                float p00,p01,p10,p11,p20,p21,p30,p31;
                upk2(st[4*z],p00,p01); upk2(st[4*z+1],p10,p11);
                upk2(st[4*z+2],p20,p21); upk2(st[4*z+3],p30,p31);
                *(float4*)(g_q + gbase + 4*z)      = make_float4(p00,p10,p20,p30);
                *(float4*)(g_q + gbase + 12 + 4*z) = make_float4(p01,p11,p21,p31);
            }
            #pragma unroll
            for (int j = 0; j < 12; j++){
                float s = wredsum(qs[j]);
                if ((tid & 31) == 0) atomicAdd(&red[j], s);
            }
        }
        #pragma unroll
        for (int d = 0; d < 12; d++) ckv[d] = fma2(ckv[d], sc2, 0ull);
        // K projection + sigmoid
        {
            u64 st[12]; float ks[12];
            #pragma unroll
            for (int j = 0; j < 12; j++){
                u64 a = pk2(fbs[12+j], fbs[12+j]);
                const ulonglong2* wv = (const ulonglong2*)(fwT + 144 + j*12);
                #pragma unroll
                for (int dp = 0; dp < 6; dp++){
                    ulonglong2 w = wv[dp];
                    a = fma2(ckv[2*dp  ], w.x, a);
                    a = fma2(ckv[2*dp+1], w.y, a);
                }
                float x0, x1; upk2(a, x0, x1);
                x0 = sigm(x0); x1 = sigm(x1);
                st[j] = pk2(x0, x1); ks[j] = x0 + x1;
            }
            #pragma unroll
            for (int z = 0; z < 3; z++){
                float p00,p01,p10,p11,p20,p21,p30,p31;
                upk2(st[4*z],p00,p01); upk2(st[4*z+1],p10,p11);
                upk2(st[4*z+2],p20,p21); upk2(st[4*z+3],p30,p31);
                *(float4*)(g_k + gbase + 4*z)      = make_float4(p00,p10,p20,p30);
                *(float4*)(g_k + gbase + 12 + 4*z) = make_float4(p01,p11,p21,p31);
            }
            #pragma unroll
            for (int j = 0; j < 12; j++){
                float s = wredsum(ks[j]);
                if ((tid & 31) == 0) atomicAdd(&red[12+j], s);
            }
        }
        // V projection
        {
            u64 st[12];
            #pragma unroll
            for (int j = 0; j < 12; j++){
                u64 a = pk2(fbs[24+j], fbs[24+j]);
                const ulonglong2* wv = (const ulonglong2*)(fwT + 288 + j*12);
                #pragma unroll
                for (int dp = 0; dp < 6; dp++){
                    ulonglong2 w = wv[dp];
                    a = fma2(ckv[2*dp  ], w.x, a);
                    a = fma2(ckv[2*dp+1], w.y, a);
                }
                st[j] = a;
            }
            #pragma unroll
            for (int z = 0; z < 3; z++){
                float p00,p01,p10,p11,p20,p21,p30,p31;
                upk2(st[4*z],p00,p01); upk2(st[4*z+1],p10,p11);
                upk2(st[4*z+2],p20,p21); upk2(st[4*z+3],p30,p31);
                *(float4*)(g_v + gbase + 4*z)      = make_float4(p00,p10,p20,p30);
                *(float4*)(g_v + gbase + 12 + 4*z) = make_float4(p01,p11,p21,p31);
            }
        }
    }
    __syncthreads();
    if (tid < 12)       atomicAdd(&g_qsum[b][tid], red[tid]);
    else if (tid < 24)  atomicAdd(&g_ksum[b][tid-12], red[tid]);
}

// ------------- K3: sink_in / src_out + sq/skv sums -------------
__global__ void __launch_bounds__(256) k3(){
    int b = blockIdx.y;
    int l = blockIdx.x*256 + threadIdx.x;
    int tid = threadIdx.x;
    __shared__ float kE[12], qE[12], red[24];
    if (tid < 12){ kE[tid] = g_ksum[b][tid] + EPSf; qE[tid] = g_qsum[b][tid] + EPSf; }
    if (tid < 24) red[tid] = 0.f;
    __syncthreads();
    size_t base = ((size_t)b*LL + l)*12;
    float q[12], k[12];
    #pragma unroll
    for (int z = 0; z < 3; z++){
        float4 a = *(const float4*)(g_q + base + 4*z);
        float4 c = *(const float4*)(g_k + base + 4*z);
        q[4*z]=a.x; q[4*z+1]=a.y; q[4*z+2]=a.z; q[4*z+3]=a.w;
        k[4*z]=c.x; k[4*z+1]=c.y; k[4*z+2]=c.z; k[4*z+3]=c.w;
    }
    float si = 0.f, so = 0.f;
    #pragma unroll
    for (int d = 0; d < 12; d++){ si += (q[d]+EPSf)*kE[d]; so += (k[d]+EPSf)*qE[d]; }
    si = 1.f/si; so = 1.f/so;
    g_si[(size_t)b*LL + l] = si;
    #pragma unroll
    for (int d = 0; d < 12; d++){
        float sqv = wredsum(q[d]*si), skvv = wredsum(k[d]*so);
        if ((tid & 31) == 0){ atomicAdd(&red[d], sqv); atomicAdd(&red[12+d], skvv); }
    }
    __syncthreads();
    if (tid < 12)      atomicAdd(&g_sq[b][tid], red[tid]);
    else if (tid < 24) atomicAdd(&g_skv[b][tid-12], red[tid]);
}

// ------------- K4: cons_src + global max -------------
__global__ void __launch_bounds__(256) k4(){
    int b = blockIdx.y;
    int l = blockIdx.x*256 + threadIdx.x;
    int tid = threadIdx.x;
    __shared__ float sqE[12];
    __shared__ int redm;
    if (tid < 12) sqE[tid] = g_sq[b][tid] + EPSf;
    if (tid == 0) redm = 0;
    __syncthreads();
    size_t base = ((size_t)b*LL + l)*12;
    float cons = 0.f;
    #pragma unroll
    for (int z = 0; z < 3; z++){
        float4 c = *(const float4*)(g_k + base + 4*z);
        cons += (c.x+EPSf)*sqE[4*z] + (c.y+EPSf)*sqE[4*z+1]
              + (c.z+EPSf)*sqE[4*z+2] + (c.w+EPSf)*sqE[4*z+3];
    }
    g_cs[(size_t)b*LL + l] = cons;
    float m = wredmax(cons);
    if ((tid & 31) == 0) atomicMax(&redm, __float_as_int(m));
    __syncthreads();
    if (tid == 0) atomicMax(&g_maxcs[b], redm);
}

// ------------- K56: sumexp + raw kv outer product (fused) -------------
__global__ void __launch_bounds__(256,1) k56(){
    int b = blockIdx.y;
    int tid = threadIdx.x;
    float mx = __int_as_float(g_maxcs[b]);
    float acc[12][12];
    #pragma unroll
    for (int d = 0; d < 12; d++)
        #pragma unroll
        for (int m = 0; m < 12; m++) acc[d][m] = 0.f;
    float se = 0.f;

    for (int l = blockIdx.x*256 + tid; l < LL; l += 64*256){
        float e = __expf(g_cs[(size_t)b*LL + l] - mx);
        se += e;
        size_t base = ((size_t)b*LL + l)*12;
        float k[12], vm[12];
        #pragma unroll
        for (int z = 0; z < 3; z++){
            float4 a = *(const float4*)(g_k + base + 4*z);
            float4 c = *(const float4*)(g_v + base + 4*z);
            k[4*z]=a.x; k[4*z+1]=a.y; k[4*z+2]=a.z; k[4*z+3]=a.w;
            vm[4*z]=c.x*e; vm[4*z+1]=c.y*e; vm[4*z+2]=c.z*e; vm[4*z+3]=c.w*e;
        }
        #pragma unroll
        for (int d = 0; d < 12; d++)
            #pragma unroll
            for (int m = 0; m < 12; m++) acc[d][m] += k[d]*vm[m];
    }
    __shared__ float red[144];
    __shared__ float sred;
    for (int i = tid; i < 144; i += 256) red[i] = 0.f;
    if (tid == 0) sred = 0.f;
    __syncthreads();
    se = wredsum(se);
    if ((tid & 31) == 0) atomicAdd(&sred, se);
    #pragma unroll
    for (int d = 0; d < 12; d++)
        #pragma unroll
        for (int m = 0; m < 12; m++){
            float v = wredsum(acc[d][m]);
            if ((tid & 31) == 0) atomicAdd(&red[d*12+m], v);
        }
    __syncthreads();
    if (tid < 144) atomicAdd(&g_kvm[b][tid], red[tid]);
    if (tid == 0)  atomicAdd(&g_sumexp[b], sred);
}

// ------------- Kmm: M = kv_norm @ Wo -------------
__global__ void kmm(const float* __restrict__ fwo){
    int b = blockIdx.x, tid = threadIdx.x;
    float norm = 172032.0f / g_sumexp[b];
    int d = tid/12, j = tid%12;
    float s = 0.f;
    #pragma unroll
    for (int m = 0; m < 12; m++) s += g_kvm[b][d*12+m]*fwo[m*12+j];
    g_M[b][tid] = s * norm;
}

// ------------- K7: epilogue, write output -------------
__global__ void __launch_bounds__(256) k7(const float* __restrict__ fbo, float* __restrict__ out){
    int b = blockIdx.y;
    int l = blockIdx.x*256 + threadIdx.x;
    int tid = threadIdx.x;
    __shared__ float Ms[144], skvE[12], bos[12];
    if (tid < 144) Ms[tid] = g_M[b][tid];
    if (tid < 12){ skvE[tid] = g_skv[b][tid] + EPSf; bos[tid] = fbo[tid]; }
    __syncthreads();
    size_t base = ((size_t)b*LL + l)*12;
    float q[12];
    #pragma unroll
    for (int z = 0; z < 3; z++){
        float4 a = *(const float4*)(g_q + base + 4*z);
        q[4*z]=a.x; q[4*z+1]=a.y; q[4*z+2]=a.z; q[4*z+3]=a.w;
    }
    float cs = 0.f;
    #pragma unroll
    for (int d = 0; d < 12; d++) cs += (q[d]+EPSf)*skvE[d];
    float scale = g_si[(size_t)b*LL + l] * sigm(cs);
    #pragma unroll
    for (int j = 0; j < 12; j++){
        float o = 0.f;
        #pragma unroll
        for (int d = 0; d < 12; d++) o += q[d]*Ms[d*12+j];
        out[((size_t)b*DD + j)*LL + l] = bos[j] + scale*o;
    }
}

extern "C" void kernel_launch(void* const* d_in, const int* in_sizes, int n_in,
                              void* d_out, int out_size){
    const float* x     = (const float*)d_in[0];
    const float* frame = (const float*)d_in[1];
    const float* wpre  = (const float*)d_in[2];
    const float* bpre  = (const float*)d_in[3];
    const float* gam   = (const float*)d_in[4];
    const float* bet   = (const float*)d_in[5];
    const float* mean  = (const float*)d_in[6];
    const float* var   = (const float*)d_in[7];
    const float* Tp    = (const float*)d_in[8];
    const float* wq    = (const float*)d_in[9];
    const float* bqc   = (const float*)d_in[10];
    const float* wkv   = (const float*)d_in[11];
    const float* bkvc  = (const float*)d_in[12];
    const float* fwq   = (const float*)d_in[13];
    const float* fbq   = (const float*)d_in[14];
    const float* fwk   = (const float*)d_in[15];
    const float* fbk   = (const float*)d_in[16];
    const float* fwv   = (const float*)d_in[17];
    const float* fbv   = (const float*)d_in[18];
    const float* fwo   = (const float*)d_in[19];
    const float* fbo   = (const float*)d_in[20];
    float* out = (float*)d_out;

    cudaFuncSetAttribute(k_conv1, cudaFuncAttributeMaxDynamicSharedMemorySize, 76288);
    cudaFuncSetAttribute(k_qkv2,  cudaFuncAttributeMaxDynamicSharedMemorySize, QKV_SMEM);

    k_init  <<<1, 1024>>>();
    k_msum  <<<dim3(168, Bn), 256>>>(frame);
    k_conv1 <<<dim3(16, 32, Bn), 256, 76288>>>(x, wpre, bpre, gam, bet, mean, var);
    k_qkv2  <<<dim3(4, FF, Bn), 256, QKV_SMEM>>>(wq, bqc, wkv, bkvc, frame, Tp,
                                                 fwq, fbq, fwk, fbk, fwv, fbv);
    k3  <<<dim3(672, Bn), 256>>>();
    k4  <<<dim3(672, Bn), 256>>>();
    k56 <<<dim3(64, Bn), 256>>>();
    kmm <<<Bn, 144>>>(fwo);
    k7  <<<dim3(672, Bn), 256>>>(fbo, out);
    (void)in_sizes; (void)n_in; (void)out_size;
}